// round 15
// baseline (speedup 1.0000x reference)
#include <cuda_runtime.h>
#include <cuda_bf16.h>
#include <cstdint>

// ---------------------------------------------------------------------------
// Problem constants
// ---------------------------------------------------------------------------
#define BATCH  4
#define SEQ    2048
#define DMODEL 1024
#define INELEM ((size_t)BATCH * SEQ * DMODEL)   // 8388608
#define WELEM  ((size_t)DMODEL * DMODEL)        // 1048576

// Scratch (device globals: allocation-free)
__device__ __nv_bfloat16 g_INh[3 * INELEM];
__device__ __nv_bfloat16 g_INl[3 * INELEM];
__device__ __nv_bfloat16 g_Wh[3 * WELEM];   // transposed W planes [n][k]
__device__ __nv_bfloat16 g_Wl[3 * WELEM];
__device__ __nv_bfloat16 g_Qh[INELEM];
__device__ __nv_bfloat16 g_Ql[INELEM];
__device__ __nv_bfloat16 g_Kh[INELEM];
__device__ __nv_bfloat16 g_Kl[INELEM];
__device__ float g_V[INELEM];                      // pre-rounded tf32 bits
__device__ float g_S[(size_t)BATCH * SEQ * SEQ];   // scores, then tf32 P

// ---------------------------------------------------------------------------
// Helpers
// ---------------------------------------------------------------------------
__device__ __forceinline__ uint32_t smem_u32(const void* p) {
    uint32_t a;
    asm("{ .reg .u64 t; cvta.to.shared.u64 t, %1; cvt.u32.u64 %0, t; }"
        : "=r"(a) : "l"(p));
    return a;
}

#define CP_ASYNC16(saddr, gptr) \
    asm volatile("cp.async.cg.shared.global [%0], [%1], 16;" \
        :: "r"(saddr), "l"(gptr) : "memory")
#define CP_COMMIT() asm volatile("cp.async.commit_group;" ::: "memory")
#define CP_WAIT0()  asm volatile("cp.async.wait_group 0;" ::: "memory")
#define CP_WAIT1()  asm volatile("cp.async.wait_group 1;" ::: "memory")

#define LDSM_X4(r0, r1, r2, r3, addr) \
    asm volatile("ldmatrix.sync.aligned.m8n8.x4.shared.b16 {%0,%1,%2,%3}, [%4];" \
        : "=r"(r0), "=r"(r1), "=r"(r2), "=r"(r3) : "r"(addr))

__device__ __forceinline__ uint32_t to_tf32(float x) {
    uint32_t t;
    asm("cvt.rna.tf32.f32 %0, %1;" : "=r"(t) : "f"(x));
    return t;
}

__device__ __forceinline__ void split_bf16(float x, __nv_bfloat16& h, __nv_bfloat16& l) {
    h = __float2bfloat16_rn(x);
    l = __float2bfloat16_rn(x - __bfloat162float(h));
}

// D += A(16x8 tf32) * B(8x8 tf32), fp32 accumulate
__device__ __forceinline__ void mma8(float* d, const uint32_t* a, const uint32_t* b) {
    asm volatile(
        "mma.sync.aligned.m16n8k8.row.col.f32.tf32.tf32.f32 "
        "{%0,%1,%2,%3}, {%4,%5,%6,%7}, {%8,%9}, {%0,%1,%2,%3};"
        : "+f"(d[0]), "+f"(d[1]), "+f"(d[2]), "+f"(d[3])
        : "r"(a[0]), "r"(a[1]), "r"(a[2]), "r"(a[3]), "r"(b[0]), "r"(b[1]));
}

// D += A(16x16 bf16) * B(16x8 bf16), fp32 accumulate
__device__ __forceinline__ void mma16bf(float* d, const uint32_t* a, const uint32_t* b) {
    asm volatile(
        "mma.sync.aligned.m16n8k16.row.col.f32.bf16.bf16.f32 "
        "{%0,%1,%2,%3}, {%4,%5,%6,%7}, {%8,%9}, {%0,%1,%2,%3};"
        : "+f"(d[0]), "+f"(d[1]), "+f"(d[2]), "+f"(d[3])
        : "r"(a[0]), "r"(a[1]), "r"(a[2]), "r"(a[3]), "r"(b[0]), "r"(b[1]));
}

// ===========================================================================
// Pre-pass 1: split query/key/value (fp32) -> bf16 hi/lo planes
// ===========================================================================
__global__ __launch_bounds__(256)
void split_in_k(const float* __restrict__ q, const float* __restrict__ k,
                const float* __restrict__ v,
                __nv_bfloat16* __restrict__ oh, __nv_bfloat16* __restrict__ ol)
{
    const float* src = (blockIdx.z == 0) ? q : ((blockIdx.z == 1) ? k : v);
    const size_t base = (size_t)blockIdx.z * INELEM;
    const size_t i = ((size_t)blockIdx.x * 256 + threadIdx.x) * 4;
    float4 x = *(const float4*)(src + i);
    __nv_bfloat16 h0, h1, h2, h3, l0, l1, l2, l3;
    split_bf16(x.x, h0, l0);
    split_bf16(x.y, h1, l1);
    split_bf16(x.z, h2, l2);
    split_bf16(x.w, h3, l3);
    __nv_bfloat162 ph0; ph0.x = h0; ph0.y = h1;
    __nv_bfloat162 ph1; ph1.x = h2; ph1.y = h3;
    __nv_bfloat162 pl0; pl0.x = l0; pl0.y = l1;
    __nv_bfloat162 pl1; pl1.x = l2; pl1.y = l3;
    *(__nv_bfloat162*)(oh + base + i)     = ph0;
    *(__nv_bfloat162*)(oh + base + i + 2) = ph1;
    *(__nv_bfloat162*)(ol + base + i)     = pl0;
    *(__nv_bfloat162*)(ol + base + i + 2) = pl1;
}

// ===========================================================================
// Pre-pass 2: transpose + split W[k][n] -> Wt planes [n][k]
// ===========================================================================
__global__ __launch_bounds__(256)
void split_w_k(const float* __restrict__ Wq, const float* __restrict__ Wk,
               const float* __restrict__ Wv,
               __nv_bfloat16* __restrict__ oh, __nv_bfloat16* __restrict__ ol)
{
    const float* W = (blockIdx.z == 0) ? Wq : ((blockIdx.z == 1) ? Wk : Wv);
    const size_t base = (size_t)blockIdx.z * WELEM;
    __shared__ float t[32][33];
    const int kb = blockIdx.y * 32;
    const int nb = blockIdx.x * 32;
    const int tx = threadIdx.x, ty = threadIdx.y;
#pragma unroll
    for (int j = 0; j < 4; j++)
        t[ty + 8 * j][tx] = W[(size_t)(kb + ty + 8 * j) * DMODEL + nb + tx];
    __syncthreads();
#pragma unroll
    for (int j = 0; j < 4; j++) {
        const float val = t[tx][ty + 8 * j];
        __nv_bfloat16 h, l;
        split_bf16(val, h, l);
        const size_t o = base + (size_t)(nb + ty + 8 * j) * DMODEL + kb + tx;
        oh[o] = h;
        ol[o] = l;
    }
}

// ===========================================================================
// bf16x3 GEMM body, ldmatrix fragments, 3-stage cp.async pipeline.
// SMEM layout per stage: A matrix then B matrix, each 128 rows x 36 words,
// row = [hi:16 words | lo:16 words | pad:4]. Row stride 36 == 4 (mod 32)
// -> ldmatrix 8-row phases hit 8 distinct 4-bank groups (conflict-free);
// lo plane is a constant +64B from hi.
//   EPI=0: fp32*alpha   EPI=1: +bias, rna-tf32 out   EPI=3: +bias, bf16 planes
// ===========================================================================
#define B3_ROWW    36
#define B3_MAT_W   (128 * B3_ROWW)     // 4608 words
#define B3_STAGE_W (2 * B3_MAT_W)      // 9216 words
#define BF3_SMEM_BYTES (3 * B3_STAGE_W * 4)   // 110592

template <int EPI, bool HASBIAS>
__device__ __forceinline__
void bf3_body(const __nv_bfloat16* __restrict__ Ah,
              const __nv_bfloat16* __restrict__ Al,
              const __nv_bfloat16* __restrict__ Bh,
              const __nv_bfloat16* __restrict__ Bl,
              const float* __restrict__ bias,
              float* __restrict__ C,
              __nv_bfloat16* __restrict__ Cbh, __nv_bfloat16* __restrict__ Cbl,
              int K, int ldk, int ldc, float alpha, int row0, int col0)
{
    extern __shared__ float smemf[];
    uint32_t* sm = (uint32_t*)smemf;

    const int tid  = threadIdx.x;
    const int wid  = tid >> 5;
    const int lane = tid & 31;
    const int tg   = lane >> 2;
    const int tk   = lane & 3;
    const int wm   = (wid >> 2) * 64;
    const int wn   = (wid & 3) * 32;

    // ldmatrix lane word-offsets (within a matrix, hi plane)
    const uint32_t aOffW = (uint32_t)((wm + (lane & 15)) * B3_ROWW + (lane >> 4) * 4);
    const uint32_t bOffW = (uint32_t)((wn + (lane & 7) + (lane >> 4) * 8) * B3_ROWW
                                      + ((lane >> 3) & 1) * 4);

    float acc[4][4][4];
#pragma unroll
    for (int mt = 0; mt < 4; mt++)
#pragma unroll
        for (int nt = 0; nt < 4; nt++)
#pragma unroll
            for (int e = 0; e < 4; e++) acc[mt][nt][e] = 0.0f;

    auto fill = [&](int st, int k0) {
        const uint32_t base = smem_u32(sm + st * B3_STAGE_W);
#pragma unroll
        for (int j = 0; j < 8; j++) {
            const __nv_bfloat16* src = (j < 2) ? Ah : ((j < 4) ? Al : ((j < 6) ? Bh : Bl));
            const int rb   = (j < 4) ? row0 : col0;
            const int mat  = (j < 4) ? 0 : B3_MAT_W;
            const int hilo = (j & 2) ? 16 : 0;         // Ah/Bh -> 0, Al/Bl -> 16
            const int t    = tid + (j & 1) * 256;      // 0..511
            const int r    = t >> 2;                   // 0..127
            const int c16  = t & 3;
            CP_ASYNC16(base + (uint32_t)(mat + r * B3_ROWW + hilo + c16 * 4) * 4u,
                       src + (size_t)(rb + r) * ldk + k0 + c16 * 8);
        }
        CP_COMMIT();
    };

    auto compute = [&](int st) {
        const uint32_t stb = smem_u32(sm + st * B3_STAGE_W);
        const uint32_t adA = stb + aOffW * 4u;                    // A hi
        const uint32_t adB = stb + (uint32_t)B3_MAT_W * 4u + bOffW * 4u;  // B hi
#pragma unroll
        for (int s = 0; s < 2; s++) {
            const uint32_t so = (uint32_t)(s * 8) * 4u;
            uint32_t bh[4][2], bl[4][2];
#pragma unroll
            for (int p = 0; p < 2; p++) {
                const uint32_t po = (uint32_t)(p * 16 * B3_ROWW) * 4u;
                LDSM_X4(bh[2 * p][0], bh[2 * p][1], bh[2 * p + 1][0], bh[2 * p + 1][1],
                        adB + po + so);
                LDSM_X4(bl[2 * p][0], bl[2 * p][1], bl[2 * p + 1][0], bl[2 * p + 1][1],
                        adB + po + so + 64u);
            }
#pragma unroll
            for (int mt = 0; mt < 4; mt++) {
                const uint32_t mo = (uint32_t)(mt * 16 * B3_ROWW) * 4u;
                uint32_t ah[4], al[4];
                LDSM_X4(ah[0], ah[1], ah[2], ah[3], adA + mo + so);
                LDSM_X4(al[0], al[1], al[2], al[3], adA + mo + so + 64u);
#pragma unroll
                for (int nt = 0; nt < 4; nt++) mma16bf(acc[mt][nt], ah, bh[nt]);
#pragma unroll
                for (int nt = 0; nt < 4; nt++) mma16bf(acc[mt][nt], ah, bl[nt]);
#pragma unroll
                for (int nt = 0; nt < 4; nt++) mma16bf(acc[mt][nt], al, bh[nt]);
            }
        }
    };

    // 3-stage mainloop, one barrier per chunk (PV-proven pattern):
    // wait1 leaves <=1 pending group (chunk i+1) so chunk i is resident;
    // barrier separates compute(i-1) reads of stage (i+2)%3 from its refill.
    const int nchunk = K / 32;
    fill(0, 0);
    fill(1, 32);
    for (int i = 0; i < nchunk; i++) {
        if (i + 1 < nchunk) { CP_WAIT1(); }
        else                { CP_WAIT0(); }
        __syncthreads();
        if (i + 2 < nchunk) fill((i + 2) % 3, (i + 2) * 32);
        compute(i % 3);
    }

    // epilogue
#pragma unroll
    for (int mt = 0; mt < 4; mt++) {
        const int r = row0 + wm + mt * 16 + tg;
#pragma unroll
        for (int nt = 0; nt < 4; nt++) {
            const int col = col0 + wn + nt * 8 + tk * 2;
            float v[4];
            v[0] = acc[mt][nt][0] * alpha;
            v[1] = acc[mt][nt][1] * alpha;
            v[2] = acc[mt][nt][2] * alpha;
            v[3] = acc[mt][nt][3] * alpha;
            if (HASBIAS) {
                const float b0 = bias[col], b1 = bias[col + 1];
                v[0] += b0; v[1] += b1;
                v[2] += b0; v[3] += b1;
            }
            if (EPI == 3) {
                __nv_bfloat16 h[4], l[4];
#pragma unroll
                for (int e = 0; e < 4; e++) split_bf16(v[e], h[e], l[e]);
                __nv_bfloat162 ph0; ph0.x = h[0]; ph0.y = h[1];
                __nv_bfloat162 pl0; pl0.x = l[0]; pl0.y = l[1];
                __nv_bfloat162 ph1; ph1.x = h[2]; ph1.y = h[3];
                __nv_bfloat162 pl1; pl1.x = l[2]; pl1.y = l[3];
                *(__nv_bfloat162*)(Cbh + (size_t)r * ldc + col)       = ph0;
                *(__nv_bfloat162*)(Cbl + (size_t)r * ldc + col)       = pl0;
                *(__nv_bfloat162*)(Cbh + (size_t)(r + 8) * ldc + col) = ph1;
                *(__nv_bfloat162*)(Cbl + (size_t)(r + 8) * ldc + col) = pl1;
            } else {
                float2 v0, v1;
                if (EPI == 1) {
                    v0 = make_float2(__uint_as_float(to_tf32(v[0])),
                                     __uint_as_float(to_tf32(v[1])));
                    v1 = make_float2(__uint_as_float(to_tf32(v[2])),
                                     __uint_as_float(to_tf32(v[3])));
                } else {
                    v0 = make_float2(v[0], v[1]);
                    v1 = make_float2(v[2], v[3]);
                }
                *(float2*)(C + (size_t)r * ldc + col)       = v0;
                *(float2*)(C + (size_t)(r + 8) * ldc + col) = v1;
            }
        }
    }
}

// ---------------------------------------------------------------------------
// Projections: bf16x3 + ldmatrix + 3-stage. grid (8, 64, 3)
// ---------------------------------------------------------------------------
__global__ __launch_bounds__(256, 2)
void proj_qkv_k(const __nv_bfloat16* __restrict__ INh,
                const __nv_bfloat16* __restrict__ INl,
                const __nv_bfloat16* __restrict__ Wh,
                const __nv_bfloat16* __restrict__ Wl,
                const float* __restrict__ bq, const float* __restrict__ bk,
                const float* __restrict__ bv,
                __nv_bfloat16* __restrict__ Qh, __nv_bfloat16* __restrict__ Ql,
                __nv_bfloat16* __restrict__ Kh, __nv_bfloat16* __restrict__ Kl,
                float* __restrict__ V)
{
    const int z = blockIdx.z;
    const __nv_bfloat16* Ah = INh + (size_t)z * INELEM;
    const __nv_bfloat16* Al = INl + (size_t)z * INELEM;
    const __nv_bfloat16* Bh = Wh + (size_t)z * WELEM;
    const __nv_bfloat16* Bl = Wl + (size_t)z * WELEM;
    const int row0 = blockIdx.y * 128;
    const int col0 = blockIdx.x * 128;
    if (z == 0)
        bf3_body<3, true>(Ah, Al, Bh, Bl, bq, nullptr, Qh, Ql,
                          DMODEL, DMODEL, DMODEL, 1.0f, row0, col0);
    else if (z == 1)
        bf3_body<3, true>(Ah, Al, Bh, Bl, bk, nullptr, Kh, Kl,
                          DMODEL, DMODEL, DMODEL, 1.0f, row0, col0);
    else
        bf3_body<1, true>(Ah, Al, Bh, Bl, bv, V, nullptr, nullptr,
                          DMODEL, DMODEL, DMODEL, 1.0f, row0, col0);
}

// ---------------------------------------------------------------------------
// Scores: bf16x3 + ldmatrix + 3-stage. grid (16, 16, 4)
// ---------------------------------------------------------------------------
__global__ __launch_bounds__(256, 2)
void scores_k(const __nv_bfloat16* __restrict__ Qh,
              const __nv_bfloat16* __restrict__ Ql,
              const __nv_bfloat16* __restrict__ Kh,
              const __nv_bfloat16* __restrict__ Kl,
              float* __restrict__ Sg)
{
    const size_t zo = (size_t)blockIdx.z * SEQ * DMODEL;
    bf3_body<0, false>(Qh + zo, Ql + zo, Kh + zo, Kl + zo, nullptr,
                       Sg + (size_t)blockIdx.z * SEQ * SEQ, nullptr, nullptr,
                       DMODEL, DMODEL, SEQ, 8.0f,
                       blockIdx.y * 128, blockIdx.x * 128);
}

// ===========================================================================
// PV body: tf32 x1, operands pre-rounded (conversion-free), 3-stage
// ===========================================================================
#define A_TILE_F 4608
#define B_TILE_F 4608
#define STAGE_F  (A_TILE_F + B_TILE_F)
#define PV_SMEM_BYTES (3 * STAGE_F * 4)

__device__ __forceinline__
void pv_body(const float* __restrict__ A, const float* __restrict__ B,
             float* __restrict__ C, int row0, int col0)
{
    extern __shared__ float smem[];
    const int K = SEQ, lda = SEQ, ldb = DMODEL, ldc = DMODEL;

    const int tid  = threadIdx.x;
    const int wid  = tid >> 5;
    const int lane = tid & 31;
    const int tg   = lane >> 2;
    const int tk   = lane & 3;
    const int wm   = (wid >> 2) * 64;
    const int wn   = (wid & 3) * 32;

    float acc[4][4][4];
#pragma unroll
    for (int mt = 0; mt < 4; mt++)
#pragma unroll
        for (int nt = 0; nt < 4; nt++)
#pragma unroll
            for (int e = 0; e < 4; e++) acc[mt][nt][e] = 0.0f;

    auto fill = [&](int st, int k0) {
        float* base = smem + st * STAGE_F;
        const uint32_t sAa = smem_u32(base);
        const uint32_t sBa = smem_u32(base + A_TILE_F);
#pragma unroll
        for (int j = 0; j < 4; j++) {
            const int idx = tid + j * 256;
            const int r  = idx >> 3;
            const int c4 = (idx & 7) << 2;
            CP_ASYNC16(sAa + (uint32_t)(r * 36 + c4) * 4u,
                       A + (size_t)(row0 + r) * lda + k0 + c4);
        }
#pragma unroll
        for (int j = 0; j < 4; j++) {
            const int idx = tid + j * 256;
            const int kk = idx >> 5;
            const int n4 = (idx & 31) << 2;
            CP_ASYNC16(sBa + (uint32_t)(kk * 136 + n4) * 4u,
                       B + (size_t)(k0 + kk) * ldb + col0 + n4);
        }
        CP_COMMIT();
    };

    auto compute = [&](int st) {
        const uint32_t* uA = (const uint32_t*)(smem + st * STAGE_F);
        const uint32_t* uB = uA + A_TILE_F;
#pragma unroll
        for (int s = 0; s < 4; s++) {
            uint32_t bh[4][2];
#pragma unroll
            for (int nt = 0; nt < 4; nt++) {
                const int n0 = wn + nt * 8;
                bh[nt][0] = uB[(s * 8 + tk)     * 136 + n0 + tg];
                bh[nt][1] = uB[(s * 8 + tk + 4) * 136 + n0 + tg];
            }
#pragma unroll
            for (int mt = 0; mt < 4; mt++) {
                const int m0 = wm + mt * 16;
                const int i0 = (m0 + tg) * 36 + s * 8 + tk;
                const int i1 = i0 + 8 * 36;
                uint32_t at[4];
                at[0] = uA[i0];
                at[1] = uA[i1];
                at[2] = uA[i0 + 4];
                at[3] = uA[i1 + 4];
#pragma unroll
                for (int nt = 0; nt < 4; nt++) mma8(acc[mt][nt], at, bh[nt]);
            }
        }
    };

    const int nchunk = K >> 5;
    fill(0, 0);
    fill(1, 32);
    for (int i = 0; i < nchunk; i++) {
        if (i + 1 < nchunk) { CP_WAIT1(); }
        else                { CP_WAIT0(); }
        __syncthreads();
        if (i + 2 < nchunk) fill((i + 2) % 3, (i + 2) << 5);
        compute(i % 3);
    }

#pragma unroll
    for (int mt = 0; mt < 4; mt++) {
        const int r = row0 + wm + mt * 16 + tg;
#pragma unroll
        for (int nt = 0; nt < 4; nt++) {
            const int col = col0 + wn + nt * 8 + tk * 2;
            *(float2*)(C + (size_t)r * ldc + col) =
                make_float2(acc[mt][nt][0], acc[mt][nt][1]);
            *(float2*)(C + (size_t)(r + 8) * ldc + col) =
                make_float2(acc[mt][nt][2], acc[mt][nt][3]);
        }
    }
}

__global__ __launch_bounds__(256, 2)
void pv_k(const float* __restrict__ Pg, const float* __restrict__ Vt,
          float* __restrict__ Og)
{
    const size_t z = blockIdx.z;
    pv_body(Pg + z * SEQ * SEQ, Vt + z * SEQ * DMODEL, Og + z * SEQ * DMODEL,
            blockIdx.y * 128, blockIdx.x * 128);
}

// ---------------------------------------------------------------------------
// JAX threefry2x32, key (0,42), partitionable scheme
// ---------------------------------------------------------------------------
__device__ __forceinline__ uint32_t threefry_mask_word(uint32_t idx)
{
    const uint32_t ks0 = 0u;
    const uint32_t ks1 = 42u;
    const uint32_t ks2 = 42u ^ 0x1BD11BDAu;
    uint32_t x0 = ks0;
    uint32_t x1 = idx + ks1;
#define TFR(r) { x0 += x1; x1 = __funnelshift_l(x1, x1, (r)); x1 ^= x0; }
    TFR(13) TFR(15) TFR(26) TFR(6)
    x0 += ks1; x1 += ks2 + 1u;
    TFR(17) TFR(29) TFR(16) TFR(24)
    x0 += ks2; x1 += ks0 + 2u;
    TFR(13) TFR(15) TFR(26) TFR(6)
    x0 += ks0; x1 += ks1 + 3u;
    TFR(17) TFR(29) TFR(16) TFR(24)
    x0 += ks1; x1 += ks2 + 4u;
    TFR(13) TFR(15) TFR(26) TFR(6)
    x0 += ks2; x1 += ks0 + 5u;
#undef TFR
    return x0 ^ x1;
}

// ---------------------------------------------------------------------------
// Softmax + dropout; P written pre-rounded tf32
// ---------------------------------------------------------------------------
__global__ __launch_bounds__(256, 4)
void softmax_dropout_k(float* __restrict__ S)
{
    const int q   = blockIdx.x;
    const int b   = blockIdx.y;
    const int tid = threadIdx.x;
    float* __restrict__ row = S + ((size_t)b * SEQ + q) * SEQ;

    float a[8];
#pragma unroll
    for (int j = 0; j < 8; j++) a[j] = row[tid + j * 256];

    float m = a[0];
#pragma unroll
    for (int j = 1; j < 8; j++) m = fmaxf(m, a[j]);
#pragma unroll
    for (int s = 16; s > 0; s >>= 1)
        m = fmaxf(m, __shfl_xor_sync(0xffffffffu, m, s));
    __shared__ float red[8];
    const int wid = tid >> 5, lane = tid & 31;
    if (lane == 0) red[wid] = m;
    __syncthreads();
    m = red[0];
#pragma unroll
    for (int w = 1; w < 8; w++) m = fmaxf(m, red[w]);
    __syncthreads();

    float s0 = 0.0f;
#pragma unroll
    for (int j = 0; j < 8; j++) {
        a[j] = __expf(a[j] - m);
        s0 += a[j];
    }
#pragma unroll
    for (int s = 16; s > 0; s >>= 1)
        s0 += __shfl_xor_sync(0xffffffffu, s0, s);
    if (lane == 0) red[wid] = s0;
    __syncthreads();
    s0 = 0.0f;
#pragma unroll
    for (int w = 0; w < 8; w++) s0 += red[w];

    const float inv = 2.0f / s0;

    const uint32_t base = ((uint32_t)(b * SEQ + q)) * (uint32_t)SEQ;
#pragma unroll
    for (int j = 0; j < 8; j++) {
        const uint32_t k = (uint32_t)tid + (uint32_t)j * 256u;
        const uint32_t w = threefry_mask_word(base + k);
        const float val = (w >> 31) ? 0.0f : a[j] * inv;
        row[k] = __uint_as_float(to_tf32(val));
    }
}

// ---------------------------------------------------------------------------
// Launcher
// ---------------------------------------------------------------------------
extern "C" void kernel_launch(void* const* d_in, const int* in_sizes, int n_in,
                              void* d_out, int out_size)
{
    (void)in_sizes; (void)n_in; (void)out_size;
    const float* query = (const float*)d_in[0];
    const float* key_  = (const float*)d_in[1];
    const float* value = (const float*)d_in[2];
    const float* Wq    = (const float*)d_in[3];
    const float* bq    = (const float*)d_in[4];
    const float* Wk    = (const float*)d_in[5];
    const float* bk    = (const float*)d_in[6];
    const float* Wv    = (const float*)d_in[7];
    const float* bv    = (const float*)d_in[8];
    float* out = (float*)d_out;

    __nv_bfloat16 *dINh, *dINl, *dWh, *dWl, *dQh, *dQl, *dKh, *dKl;
    float *dV, *dS;
    cudaGetSymbolAddress((void**)&dINh, g_INh);
    cudaGetSymbolAddress((void**)&dINl, g_INl);
    cudaGetSymbolAddress((void**)&dWh,  g_Wh);
    cudaGetSymbolAddress((void**)&dWl,  g_Wl);
    cudaGetSymbolAddress((void**)&dQh,  g_Qh);
    cudaGetSymbolAddress((void**)&dQl,  g_Ql);
    cudaGetSymbolAddress((void**)&dKh,  g_Kh);
    cudaGetSymbolAddress((void**)&dKl,  g_Kl);
    cudaGetSymbolAddress((void**)&dV,   g_V);
    cudaGetSymbolAddress((void**)&dS,   g_S);

    static bool attr_done = false;
    if (!attr_done) {
        cudaFuncSetAttribute(proj_qkv_k,
                             cudaFuncAttributeMaxDynamicSharedMemorySize, BF3_SMEM_BYTES);
        cudaFuncSetAttribute(scores_k,
                             cudaFuncAttributeMaxDynamicSharedMemorySize, BF3_SMEM_BYTES);
        cudaFuncSetAttribute(pv_k,
                             cudaFuncAttributeMaxDynamicSharedMemorySize, PV_SMEM_BYTES);
        attr_done = true;
    }

    dim3 thr(256);

    // 0a) split inputs -> bf16 planes
    dim3 gSI(INELEM / (256 * 4), 1, 3);
    split_in_k<<<gSI, thr>>>(query, key_, value, dINh, dINl);

    // 0b) transpose + split W -> K-major bf16 planes
    dim3 gSW(DMODEL / 32, DMODEL / 32, 3);
    split_w_k<<<gSW, dim3(32, 8)>>>(Wq, Wk, Wv, dWh, dWl);

    // 1) Projections Q,K,V — bf16x3 + ldmatrix + 3-stage
    dim3 gP(DMODEL / 128, (BATCH * SEQ) / 128, 3);
    proj_qkv_k<<<gP, thr, BF3_SMEM_BYTES>>>(dINh, dINl, dWh, dWl,
                                            bq, bk, bv,
                                            dQh, dQl, dKh, dKl, dV);

    // 2) Scores — bf16x3 + ldmatrix + 3-stage
    dim3 gS(SEQ / 128, SEQ / 128, BATCH);
    scores_k<<<gS, thr, BF3_SMEM_BYTES>>>(dQh, dQl, dKh, dKl, dS);

    // 3) Softmax + threefry dropout; P pre-rounded tf32
    dim3 gSm(SEQ, BATCH, 1);
    softmax_dropout_k<<<gSm, thr>>>(dS);

    // 4) O = P @ Vt (conversion-free tf32 x1)
    dim3 gO(DMODEL / 128, SEQ / 128, BATCH);
    pv_k<<<gO, thr, PV_SMEM_BYTES>>>(dS, dV, out);
}

// round 16
// speedup vs baseline: 1.0161x; 1.0161x over previous
#include <cuda_runtime.h>
#include <cuda_bf16.h>
#include <cstdint>

// ---------------------------------------------------------------------------
// Problem constants
// ---------------------------------------------------------------------------
#define BATCH  4
#define SEQ    2048
#define DMODEL 1024
#define INELEM ((size_t)BATCH * SEQ * DMODEL)   // 8388608
#define WELEM  ((size_t)DMODEL * DMODEL)        // 1048576

// Scratch (device globals: allocation-free)
__device__ __nv_bfloat16 g_INh[3 * INELEM];
__device__ __nv_bfloat16 g_INl[3 * INELEM];
__device__ __nv_bfloat16 g_Wh[3 * WELEM];   // transposed W planes [n][k]
__device__ __nv_bfloat16 g_Wl[3 * WELEM];
__device__ __nv_bfloat16 g_Qh[INELEM];
__device__ __nv_bfloat16 g_Ql[INELEM];
__device__ __nv_bfloat16 g_Kh[INELEM];
__device__ __nv_bfloat16 g_Kl[INELEM];
__device__ float g_V [INELEM];                     // V proj, tf32 bits, [b][t][d]
__device__ float g_Vt[INELEM];                     // V transposed, [b][d][t]
__device__ float g_S[(size_t)BATCH * SEQ * SEQ];   // scores, then tf32 P

// ---------------------------------------------------------------------------
// Helpers
// ---------------------------------------------------------------------------
__device__ __forceinline__ uint32_t smem_u32(const void* p) {
    uint32_t a;
    asm("{ .reg .u64 t; cvta.to.shared.u64 t, %1; cvt.u32.u64 %0, t; }"
        : "=r"(a) : "l"(p));
    return a;
}

#define CP_ASYNC16(saddr, gptr) \
    asm volatile("cp.async.cg.shared.global [%0], [%1], 16;" \
        :: "r"(saddr), "l"(gptr) : "memory")
#define CP_COMMIT() asm volatile("cp.async.commit_group;" ::: "memory")
#define CP_WAIT0()  asm volatile("cp.async.wait_group 0;" ::: "memory")
#define CP_WAIT1()  asm volatile("cp.async.wait_group 1;" ::: "memory")

#define LDSM_X4(r0, r1, r2, r3, addr) \
    asm volatile("ldmatrix.sync.aligned.m8n8.x4.shared.b16 {%0,%1,%2,%3}, [%4];" \
        : "=r"(r0), "=r"(r1), "=r"(r2), "=r"(r3) : "r"(addr))

__device__ __forceinline__ uint32_t to_tf32(float x) {
    uint32_t t;
    asm("cvt.rna.tf32.f32 %0, %1;" : "=r"(t) : "f"(x));
    return t;
}

__device__ __forceinline__ void split_bf16(float x, __nv_bfloat16& h, __nv_bfloat16& l) {
    h = __float2bfloat16_rn(x);
    l = __float2bfloat16_rn(x - __bfloat162float(h));
}

// D += A(16x8 tf32) * B(8x8 tf32), fp32 accumulate
__device__ __forceinline__ void mma8(float* d, const uint32_t* a, const uint32_t* b) {
    asm volatile(
        "mma.sync.aligned.m16n8k8.row.col.f32.tf32.tf32.f32 "
        "{%0,%1,%2,%3}, {%4,%5,%6,%7}, {%8,%9}, {%0,%1,%2,%3};"
        : "+f"(d[0]), "+f"(d[1]), "+f"(d[2]), "+f"(d[3])
        : "r"(a[0]), "r"(a[1]), "r"(a[2]), "r"(a[3]), "r"(b[0]), "r"(b[1]));
}

// D += A(16x16 bf16) * B(16x8 bf16), fp32 accumulate
__device__ __forceinline__ void mma16bf(float* d, const uint32_t* a, const uint32_t* b) {
    asm volatile(
        "mma.sync.aligned.m16n8k16.row.col.f32.bf16.bf16.f32 "
        "{%0,%1,%2,%3}, {%4,%5,%6,%7}, {%8,%9}, {%0,%1,%2,%3};"
        : "+f"(d[0]), "+f"(d[1]), "+f"(d[2]), "+f"(d[3])
        : "r"(a[0]), "r"(a[1]), "r"(a[2]), "r"(a[3]), "r"(b[0]), "r"(b[1]));
}

// ===========================================================================
// Pre-pass 1: split query/key/value (fp32) -> bf16 hi/lo planes
// ===========================================================================
__global__ __launch_bounds__(256)
void split_in_k(const float* __restrict__ q, const float* __restrict__ k,
                const float* __restrict__ v,
                __nv_bfloat16* __restrict__ oh, __nv_bfloat16* __restrict__ ol)
{
    const float* src = (blockIdx.z == 0) ? q : ((blockIdx.z == 1) ? k : v);
    const size_t base = (size_t)blockIdx.z * INELEM;
    const size_t i = ((size_t)blockIdx.x * 256 + threadIdx.x) * 4;
    float4 x = *(const float4*)(src + i);
    __nv_bfloat16 h0, h1, h2, h3, l0, l1, l2, l3;
    split_bf16(x.x, h0, l0);
    split_bf16(x.y, h1, l1);
    split_bf16(x.z, h2, l2);
    split_bf16(x.w, h3, l3);
    __nv_bfloat162 ph0; ph0.x = h0; ph0.y = h1;
    __nv_bfloat162 ph1; ph1.x = h2; ph1.y = h3;
    __nv_bfloat162 pl0; pl0.x = l0; pl0.y = l1;
    __nv_bfloat162 pl1; pl1.x = l2; pl1.y = l3;
    *(__nv_bfloat162*)(oh + base + i)     = ph0;
    *(__nv_bfloat162*)(oh + base + i + 2) = ph1;
    *(__nv_bfloat162*)(ol + base + i)     = pl0;
    *(__nv_bfloat162*)(ol + base + i + 2) = pl1;
}

// ===========================================================================
// Pre-pass 2: transpose + split W[k][n] -> Wt planes [n][k]
// ===========================================================================
__global__ __launch_bounds__(256)
void split_w_k(const float* __restrict__ Wq, const float* __restrict__ Wk,
               const float* __restrict__ Wv,
               __nv_bfloat16* __restrict__ oh, __nv_bfloat16* __restrict__ ol)
{
    const float* W = (blockIdx.z == 0) ? Wq : ((blockIdx.z == 1) ? Wk : Wv);
    const size_t base = (size_t)blockIdx.z * WELEM;
    __shared__ float t[32][33];
    const int kb = blockIdx.y * 32;
    const int nb = blockIdx.x * 32;
    const int tx = threadIdx.x, ty = threadIdx.y;
#pragma unroll
    for (int j = 0; j < 4; j++)
        t[ty + 8 * j][tx] = W[(size_t)(kb + ty + 8 * j) * DMODEL + nb + tx];
    __syncthreads();
#pragma unroll
    for (int j = 0; j < 4; j++) {
        const float val = t[tx][ty + 8 * j];
        __nv_bfloat16 h, l;
        split_bf16(val, h, l);
        const size_t o = base + (size_t)(nb + ty + 8 * j) * DMODEL + kb + tx;
        oh[o] = h;
        ol[o] = l;
    }
}

// ===========================================================================
// Pre-pass 3 (post-proj): transpose V[b][t][d] -> Vt[b][d][t], coalesced
// ===========================================================================
__global__ __launch_bounds__(256)
void transpose_v_k(const float* __restrict__ V, float* __restrict__ Vt)
{
    __shared__ float t[32][33];
    const size_t zb = (size_t)blockIdx.z * SEQ * DMODEL;
    const int tb = blockIdx.y * 32;   // token base
    const int db = blockIdx.x * 32;   // dmodel base
    const int tx = threadIdx.x, ty = threadIdx.y;
#pragma unroll
    for (int j = 0; j < 4; j++)
        t[ty + 8 * j][tx] = V[zb + (size_t)(tb + ty + 8 * j) * DMODEL + db + tx];
    __syncthreads();
#pragma unroll
    for (int j = 0; j < 4; j++)
        Vt[zb + (size_t)(db + ty + 8 * j) * SEQ + tb + tx] = t[tx][ty + 8 * j];
}

// ===========================================================================
// bf16x3 GEMM body with ldmatrix fragment loads (R14-proven 2-stage config).
// A planes [Mrows, K] k-contig (row0), B planes [Nrows, K] k-contig (col0).
// KC=32 (2 k16-steps), 256 thr, 8 warps 64x32, 20-word row pitch.
//   EPI=0: fp32*alpha   EPI=1: +bias, rna-tf32 out   EPI=3: +bias, bf16 planes
// ===========================================================================
#define SC_ROWW    20
#define SC_PLANE_W (128 * SC_ROWW)       // 2560 words
#define SC_STAGE_W (4 * SC_PLANE_W)      // 10240 words
#define BF3_SMEM_BYTES (2 * SC_STAGE_W * 4)   // 81920

template <int EPI, bool HASBIAS>
__device__ __forceinline__
void bf3_body(const __nv_bfloat16* __restrict__ Ah,
              const __nv_bfloat16* __restrict__ Al,
              const __nv_bfloat16* __restrict__ Bh,
              const __nv_bfloat16* __restrict__ Bl,
              const float* __restrict__ bias,
              float* __restrict__ C,
              __nv_bfloat16* __restrict__ Cbh, __nv_bfloat16* __restrict__ Cbl,
              int K, int ldk, int ldc, float alpha, int row0, int col0)
{
    extern __shared__ float smemf[];
    uint32_t* sm = (uint32_t*)smemf;

    const int tid  = threadIdx.x;
    const int wid  = tid >> 5;
    const int lane = tid & 31;
    const int tg   = lane >> 2;
    const int tk   = lane & 3;
    const int wm   = (wid >> 2) * 64;
    const int wn   = (wid & 3) * 32;

    const uint32_t aOffW = (uint32_t)((wm + (lane & 15)) * SC_ROWW + (lane >> 4) * 4);
    const uint32_t bOffW = (uint32_t)((wn + (lane & 7) + (lane >> 4) * 8) * SC_ROWW
                                      + ((lane >> 3) & 1) * 4);

    float acc[4][4][4];
#pragma unroll
    for (int mt = 0; mt < 4; mt++)
#pragma unroll
        for (int nt = 0; nt < 4; nt++)
#pragma unroll
            for (int e = 0; e < 4; e++) acc[mt][nt][e] = 0.0f;

    auto fill = [&](int st, int k0) {
        const uint32_t base = smem_u32(sm + st * SC_STAGE_W);
#pragma unroll
        for (int j = 0; j < 8; j++) {
            const __nv_bfloat16* src = (j < 2) ? Ah : ((j < 4) ? Al : ((j < 6) ? Bh : Bl));
            const int rb  = (j < 4) ? row0 : col0;
            const int pl  = j >> 1;
            const int t   = tid + (j & 1) * 256;
            const int r   = t >> 2;
            const int c16 = t & 3;
            CP_ASYNC16(base + (uint32_t)(pl * SC_PLANE_W + r * SC_ROWW + c16 * 4) * 4u,
                       src + (size_t)(rb + r) * ldk + k0 + c16 * 8);
        }
        CP_COMMIT();
    };

    auto compute = [&](int st) {
        const uint32_t stb = smem_u32(sm + st * SC_STAGE_W);
        const uint32_t adAh = stb + aOffW * 4u;
        const uint32_t adAl = adAh + SC_PLANE_W * 4u;
        const uint32_t adBh = stb + 2u * SC_PLANE_W * 4u + bOffW * 4u;
        const uint32_t adBl = adBh + SC_PLANE_W * 4u;
#pragma unroll
        for (int s = 0; s < 2; s++) {
            const uint32_t so = (uint32_t)(s * 8) * 4u;
            uint32_t bh[4][2], bl[4][2];
#pragma unroll
            for (int p = 0; p < 2; p++) {
                const uint32_t po = (uint32_t)(p * 16 * SC_ROWW) * 4u;
                LDSM_X4(bh[2 * p][0], bh[2 * p][1], bh[2 * p + 1][0], bh[2 * p + 1][1],
                        adBh + po + so);
                LDSM_X4(bl[2 * p][0], bl[2 * p][1], bl[2 * p + 1][0], bl[2 * p + 1][1],
                        adBl + po + so);
            }
#pragma unroll
            for (int mt = 0; mt < 4; mt++) {
                const uint32_t mo = (uint32_t)(mt * 16 * SC_ROWW) * 4u;
                uint32_t ah[4], al[4];
                LDSM_X4(ah[0], ah[1], ah[2], ah[3], adAh + mo + so);
                LDSM_X4(al[0], al[1], al[2], al[3], adAl + mo + so);
#pragma unroll
                for (int nt = 0; nt < 4; nt++) mma16bf(acc[mt][nt], ah, bh[nt]);
#pragma unroll
                for (int nt = 0; nt < 4; nt++) mma16bf(acc[mt][nt], ah, bl[nt]);
#pragma unroll
                for (int nt = 0; nt < 4; nt++) mma16bf(acc[mt][nt], al, bh[nt]);
            }
        }
    };

    const int nchunk = K / 32;
    fill(0, 0);
    for (int i = 0; i < nchunk; i++) {
        CP_WAIT0();
        __syncthreads();
        if (i + 1 < nchunk) fill((i + 1) & 1, (i + 1) * 32);
        compute(i & 1);
    }

    // epilogue
#pragma unroll
    for (int mt = 0; mt < 4; mt++) {
        const int r = row0 + wm + mt * 16 + tg;
#pragma unroll
        for (int nt = 0; nt < 4; nt++) {
            const int col = col0 + wn + nt * 8 + tk * 2;
            float v[4];
            v[0] = acc[mt][nt][0] * alpha;
            v[1] = acc[mt][nt][1] * alpha;
            v[2] = acc[mt][nt][2] * alpha;
            v[3] = acc[mt][nt][3] * alpha;
            if (HASBIAS) {
                const float b0 = bias[col], b1 = bias[col + 1];
                v[0] += b0; v[1] += b1;
                v[2] += b0; v[3] += b1;
            }
            if (EPI == 3) {
                __nv_bfloat16 h[4], l[4];
#pragma unroll
                for (int e = 0; e < 4; e++) split_bf16(v[e], h[e], l[e]);
                __nv_bfloat162 ph0; ph0.x = h[0]; ph0.y = h[1];
                __nv_bfloat162 pl0; pl0.x = l[0]; pl0.y = l[1];
                __nv_bfloat162 ph1; ph1.x = h[2]; ph1.y = h[3];
                __nv_bfloat162 pl1; pl1.x = l[2]; pl1.y = l[3];
                *(__nv_bfloat162*)(Cbh + (size_t)r * ldc + col)       = ph0;
                *(__nv_bfloat162*)(Cbl + (size_t)r * ldc + col)       = pl0;
                *(__nv_bfloat162*)(Cbh + (size_t)(r + 8) * ldc + col) = ph1;
                *(__nv_bfloat162*)(Cbl + (size_t)(r + 8) * ldc + col) = pl1;
            } else {
                float2 v0, v1;
                if (EPI == 1) {
                    v0 = make_float2(__uint_as_float(to_tf32(v[0])),
                                     __uint_as_float(to_tf32(v[1])));
                    v1 = make_float2(__uint_as_float(to_tf32(v[2])),
                                     __uint_as_float(to_tf32(v[3])));
                } else {
                    v0 = make_float2(v[0], v[1]);
                    v1 = make_float2(v[2], v[3]);
                }
                *(float2*)(C + (size_t)r * ldc + col)       = v0;
                *(float2*)(C + (size_t)(r + 8) * ldc + col) = v1;
            }
        }
    }
}

// ---------------------------------------------------------------------------
// Projections: bf16x3 + ldmatrix. grid (8, 64, 3)
// ---------------------------------------------------------------------------
__global__ __launch_bounds__(256, 2)
void proj_qkv_k(const __nv_bfloat16* __restrict__ INh,
                const __nv_bfloat16* __restrict__ INl,
                const __nv_bfloat16* __restrict__ Wh,
                const __nv_bfloat16* __restrict__ Wl,
                const float* __restrict__ bq, const float* __restrict__ bk,
                const float* __restrict__ bv,
                __nv_bfloat16* __restrict__ Qh, __nv_bfloat16* __restrict__ Ql,
                __nv_bfloat16* __restrict__ Kh, __nv_bfloat16* __restrict__ Kl,
                float* __restrict__ V)
{
    const int z = blockIdx.z;
    const __nv_bfloat16* Ah = INh + (size_t)z * INELEM;
    const __nv_bfloat16* Al = INl + (size_t)z * INELEM;
    const __nv_bfloat16* Bh = Wh + (size_t)z * WELEM;
    const __nv_bfloat16* Bl = Wl + (size_t)z * WELEM;
    const int row0 = blockIdx.y * 128;
    const int col0 = blockIdx.x * 128;
    if (z == 0)
        bf3_body<3, true>(Ah, Al, Bh, Bl, bq, nullptr, Qh, Ql,
                          DMODEL, DMODEL, DMODEL, 1.0f, row0, col0);
    else if (z == 1)
        bf3_body<3, true>(Ah, Al, Bh, Bl, bk, nullptr, Kh, Kl,
                          DMODEL, DMODEL, DMODEL, 1.0f, row0, col0);
    else
        bf3_body<1, true>(Ah, Al, Bh, Bl, bv, V, nullptr, nullptr,
                          DMODEL, DMODEL, DMODEL, 1.0f, row0, col0);
}

// ---------------------------------------------------------------------------
// Scores: bf16x3 + ldmatrix. grid (16, 16, 4)
// ---------------------------------------------------------------------------
__global__ __launch_bounds__(256, 2)
void scores_k(const __nv_bfloat16* __restrict__ Qh,
              const __nv_bfloat16* __restrict__ Ql,
              const __nv_bfloat16* __restrict__ Kh,
              const __nv_bfloat16* __restrict__ Kl,
              float* __restrict__ Sg)
{
    const size_t zo = (size_t)blockIdx.z * SEQ * DMODEL;
    bf3_body<0, false>(Qh + zo, Ql + zo, Kh + zo, Kl + zo, nullptr,
                       Sg + (size_t)blockIdx.z * SEQ * SEQ, nullptr, nullptr,
                       DMODEL, DMODEL, SEQ, 8.0f,
                       blockIdx.y * 128, blockIdx.x * 128);
}

// ===========================================================================
// PV body: tf32 x1, BOTH tiles [rows][k] k-contig (P row-major, Vt [d][t]).
// Fragments via ldmatrix.b16 reinterpretation: "word j of row r -> lane 4r+j"
// is exactly the tf32 fragment mapping. 36-word row pitch (conflict-free
// 8-row phases), 3-stage cp.async, conversion-free.
// ===========================================================================
#define PV_ROWW    36
#define PV_TILE_W  (128 * PV_ROWW)        // 4608 words
#define PV_STAGE_W (2 * PV_TILE_W)        // 9216 words
#define PV_SMEM_BYTES (3 * PV_STAGE_W * 4)   // 110592

__device__ __forceinline__
void pv_body(const float* __restrict__ A, const float* __restrict__ Bt,
             float* __restrict__ C, int row0, int col0)
{
    extern __shared__ float smem[];
    uint32_t* sm = (uint32_t*)smem;
    const int K = SEQ, lda = SEQ, ldb = SEQ, ldc = DMODEL;

    const int tid  = threadIdx.x;
    const int wid  = tid >> 5;
    const int lane = tid & 31;
    const int tg   = lane >> 2;
    const int tk   = lane & 3;
    const int wm   = (wid >> 2) * 64;
    const int wn   = (wid & 3) * 32;

    const uint32_t aOffW = (uint32_t)((wm + (lane & 15)) * PV_ROWW + (lane >> 4) * 4);
    const uint32_t bOffW = (uint32_t)((wn + (lane & 7) + (lane >> 4) * 8) * PV_ROWW
                                      + ((lane >> 3) & 1) * 4);

    float acc[4][4][4];
#pragma unroll
    for (int mt = 0; mt < 4; mt++)
#pragma unroll
        for (int nt = 0; nt < 4; nt++)
#pragma unroll
            for (int e = 0; e < 4; e++) acc[mt][nt][e] = 0.0f;

    auto fill = [&](int st, int k0) {
        const uint32_t base = smem_u32(sm + st * PV_STAGE_W);
#pragma unroll
        for (int j = 0; j < 4; j++) {
            const int idx = tid + j * 256;
            const int r  = idx >> 3;
            const int c4 = (idx & 7) << 2;
            CP_ASYNC16(base + (uint32_t)(r * PV_ROWW + c4) * 4u,
                       A + (size_t)(row0 + r) * lda + k0 + c4);
        }
#pragma unroll
        for (int j = 0; j < 4; j++) {
            const int idx = tid + j * 256;
            const int r  = idx >> 3;
            const int c4 = (idx & 7) << 2;
            CP_ASYNC16(base + (uint32_t)(PV_TILE_W + r * PV_ROWW + c4) * 4u,
                       Bt + (size_t)(col0 + r) * ldb + k0 + c4);
        }
        CP_COMMIT();
    };

    auto compute = [&](int st) {
        const uint32_t stb = smem_u32(sm + st * PV_STAGE_W);
        const uint32_t adA = stb + aOffW * 4u;
        const uint32_t adB = stb + (uint32_t)PV_TILE_W * 4u + bOffW * 4u;
#pragma unroll
        for (int s = 0; s < 4; s++) {
            const uint32_t so = (uint32_t)(s * 8) * 4u;
            uint32_t bh[4][2];
#pragma unroll
            for (int p = 0; p < 2; p++) {
                const uint32_t po = (uint32_t)(p * 16 * PV_ROWW) * 4u;
                LDSM_X4(bh[2 * p][0], bh[2 * p][1], bh[2 * p + 1][0], bh[2 * p + 1][1],
                        adB + po + so);
            }
#pragma unroll
            for (int mt = 0; mt < 4; mt++) {
                const uint32_t mo = (uint32_t)(mt * 16 * PV_ROWW) * 4u;
                uint32_t at[4];
                LDSM_X4(at[0], at[1], at[2], at[3], adA + mo + so);
#pragma unroll
                for (int nt = 0; nt < 4; nt++) mma8(acc[mt][nt], at, bh[nt]);
            }
        }
    };

    const int nchunk = K >> 5;
    fill(0, 0);
    fill(1, 32);
    for (int i = 0; i < nchunk; i++) {
        if (i + 1 < nchunk) { CP_WAIT1(); }
        else                { CP_WAIT0(); }
        __syncthreads();
        if (i + 2 < nchunk) fill((i + 2) % 3, (i + 2) << 5);
        compute(i % 3);
    }

#pragma unroll
    for (int mt = 0; mt < 4; mt++) {
        const int r = row0 + wm + mt * 16 + tg;
#pragma unroll
        for (int nt = 0; nt < 4; nt++) {
            const int col = col0 + wn + nt * 8 + tk * 2;
            *(float2*)(C + (size_t)r * ldc + col) =
                make_float2(acc[mt][nt][0], acc[mt][nt][1]);
            *(float2*)(C + (size_t)(r + 8) * ldc + col) =
                make_float2(acc[mt][nt][2], acc[mt][nt][3]);
        }
    }
}

__global__ __launch_bounds__(256, 2)
void pv_k(const float* __restrict__ Pg, const float* __restrict__ Vt,
          float* __restrict__ Og)
{
    const size_t z = blockIdx.z;
    pv_body(Pg + z * SEQ * SEQ, Vt + z * SEQ * DMODEL, Og + z * SEQ * DMODEL,
            blockIdx.y * 128, blockIdx.x * 128);
}

// ---------------------------------------------------------------------------
// JAX threefry2x32, key (0,42), partitionable scheme
// ---------------------------------------------------------------------------
__device__ __forceinline__ uint32_t threefry_mask_word(uint32_t idx)
{
    const uint32_t ks0 = 0u;
    const uint32_t ks1 = 42u;
    const uint32_t ks2 = 42u ^ 0x1BD11BDAu;
    uint32_t x0 = ks0;
    uint32_t x1 = idx + ks1;
#define TFR(r) { x0 += x1; x1 = __funnelshift_l(x1, x1, (r)); x1 ^= x0; }
    TFR(13) TFR(15) TFR(26) TFR(6)
    x0 += ks1; x1 += ks2 + 1u;
    TFR(17) TFR(29) TFR(16) TFR(24)
    x0 += ks2; x1 += ks0 + 2u;
    TFR(13) TFR(15) TFR(26) TFR(6)
    x0 += ks0; x1 += ks1 + 3u;
    TFR(17) TFR(29) TFR(16) TFR(24)
    x0 += ks1; x1 += ks2 + 4u;
    TFR(13) TFR(15) TFR(26) TFR(6)
    x0 += ks2; x1 += ks0 + 5u;
#undef TFR
    return x0 ^ x1;
}

// ---------------------------------------------------------------------------
// Softmax + dropout; P written pre-rounded tf32 (row-major, unchanged)
// ---------------------------------------------------------------------------
__global__ __launch_bounds__(256, 4)
void softmax_dropout_k(float* __restrict__ S)
{
    const int q   = blockIdx.x;
    const int b   = blockIdx.y;
    const int tid = threadIdx.x;
    float* __restrict__ row = S + ((size_t)b * SEQ + q) * SEQ;

    float a[8];
#pragma unroll
    for (int j = 0; j < 8; j++) a[j] = row[tid + j * 256];

    float m = a[0];
#pragma unroll
    for (int j = 1; j < 8; j++) m = fmaxf(m, a[j]);
#pragma unroll
    for (int s = 16; s > 0; s >>= 1)
        m = fmaxf(m, __shfl_xor_sync(0xffffffffu, m, s));
    __shared__ float red[8];
    const int wid = tid >> 5, lane = tid & 31;
    if (lane == 0) red[wid] = m;
    __syncthreads();
    m = red[0];
#pragma unroll
    for (int w = 1; w < 8; w++) m = fmaxf(m, red[w]);
    __syncthreads();

    float s0 = 0.0f;
#pragma unroll
    for (int j = 0; j < 8; j++) {
        a[j] = __expf(a[j] - m);
        s0 += a[j];
    }
#pragma unroll
    for (int s = 16; s > 0; s >>= 1)
        s0 += __shfl_xor_sync(0xffffffffu, s0, s);
    if (lane == 0) red[wid] = s0;
    __syncthreads();
    s0 = 0.0f;
#pragma unroll
    for (int w = 0; w < 8; w++) s0 += red[w];

    const float inv = 2.0f / s0;

    const uint32_t base = ((uint32_t)(b * SEQ + q)) * (uint32_t)SEQ;
#pragma unroll
    for (int j = 0; j < 8; j++) {
        const uint32_t k = (uint32_t)tid + (uint32_t)j * 256u;
        const uint32_t w = threefry_mask_word(base + k);
        const float val = (w >> 31) ? 0.0f : a[j] * inv;
        row[k] = __uint_as_float(to_tf32(val));
    }
}

// ---------------------------------------------------------------------------
// Launcher
// ---------------------------------------------------------------------------
extern "C" void kernel_launch(void* const* d_in, const int* in_sizes, int n_in,
                              void* d_out, int out_size)
{
    (void)in_sizes; (void)n_in; (void)out_size;
    const float* query = (const float*)d_in[0];
    const float* key_  = (const float*)d_in[1];
    const float* value = (const float*)d_in[2];
    const float* Wq    = (const float*)d_in[3];
    const float* bq    = (const float*)d_in[4];
    const float* Wk    = (const float*)d_in[5];
    const float* bk    = (const float*)d_in[6];
    const float* Wv    = (const float*)d_in[7];
    const float* bv    = (const float*)d_in[8];
    float* out = (float*)d_out;

    __nv_bfloat16 *dINh, *dINl, *dWh, *dWl, *dQh, *dQl, *dKh, *dKl;
    float *dV, *dVt, *dS;
    cudaGetSymbolAddress((void**)&dINh, g_INh);
    cudaGetSymbolAddress((void**)&dINl, g_INl);
    cudaGetSymbolAddress((void**)&dWh,  g_Wh);
    cudaGetSymbolAddress((void**)&dWl,  g_Wl);
    cudaGetSymbolAddress((void**)&dQh,  g_Qh);
    cudaGetSymbolAddress((void**)&dQl,  g_Ql);
    cudaGetSymbolAddress((void**)&dKh,  g_Kh);
    cudaGetSymbolAddress((void**)&dKl,  g_Kl);
    cudaGetSymbolAddress((void**)&dV,   g_V);
    cudaGetSymbolAddress((void**)&dVt,  g_Vt);
    cudaGetSymbolAddress((void**)&dS,   g_S);

    static bool attr_done = false;
    if (!attr_done) {
        cudaFuncSetAttribute(proj_qkv_k,
                             cudaFuncAttributeMaxDynamicSharedMemorySize, BF3_SMEM_BYTES);
        cudaFuncSetAttribute(scores_k,
                             cudaFuncAttributeMaxDynamicSharedMemorySize, BF3_SMEM_BYTES);
        cudaFuncSetAttribute(pv_k,
                             cudaFuncAttributeMaxDynamicSharedMemorySize, PV_SMEM_BYTES);
        attr_done = true;
    }

    dim3 thr(256);

    // 0a) split inputs -> bf16 planes
    dim3 gSI(INELEM / (256 * 4), 1, 3);
    split_in_k<<<gSI, thr>>>(query, key_, value, dINh, dINl);

    // 0b) transpose + split W -> K-major bf16 planes
    dim3 gSW(DMODEL / 32, DMODEL / 32, 3);
    split_w_k<<<gSW, dim3(32, 8)>>>(Wq, Wk, Wv, dWh, dWl);

    // 1) Projections Q,K,V — bf16x3 + ldmatrix
    dim3 gP(DMODEL / 128, (BATCH * SEQ) / 128, 3);
    proj_qkv_k<<<gP, thr, BF3_SMEM_BYTES>>>(dINh, dINl, dWh, dWl,
                                            bq, bk, bv,
                                            dQh, dQl, dKh, dKl, dV);

    // 1b) transpose V -> Vt [b][d][t] for PV's ldmatrix-tf32 fragments
    dim3 gTV(DMODEL / 32, SEQ / 32, BATCH);
    transpose_v_k<<<gTV, dim3(32, 8)>>>(dV, dVt);

    // 2) Scores — bf16x3 + ldmatrix
    dim3 gS(SEQ / 128, SEQ / 128, BATCH);
    scores_k<<<gS, thr, BF3_SMEM_BYTES>>>(dQh, dQl, dKh, dKl, dS);

    // 3) Softmax + threefry dropout; P pre-rounded tf32
    dim3 gSm(SEQ, BATCH, 1);
    softmax_dropout_k<<<gSm, thr>>>(dS);

    // 4) O = P @ Vt — tf32 x1, ldmatrix fragments (b16 reinterpretation)
    dim3 gO(DMODEL / 128, SEQ / 128, BATCH);
    pv_k<<<gO, thr, PV_SMEM_BYTES>>>(dS, dVt, out);
}

// round 17
// speedup vs baseline: 1.0622x; 1.0454x over previous
#include <cuda_runtime.h>
#include <cuda_bf16.h>
#include <cstdint>

// ---------------------------------------------------------------------------
// Problem constants
// ---------------------------------------------------------------------------
#define BATCH  4
#define SEQ    2048
#define DMODEL 1024
#define INELEM ((size_t)BATCH * SEQ * DMODEL)   // 8388608
#define WELEM  ((size_t)DMODEL * DMODEL)        // 1048576

// Scratch (device globals: allocation-free)
__device__ __nv_bfloat16 g_INh[2 * INELEM];        // q,k bf16 hi planes
__device__ __nv_bfloat16 g_INl[2 * INELEM];        // q,k bf16 lo planes
__device__ float g_Vin[INELEM];                    // v rounded tf32
__device__ __nv_bfloat16 g_Wh[2 * WELEM];          // Wq,Wk transposed hi [n][k]
__device__ __nv_bfloat16 g_Wl[2 * WELEM];
__device__ float g_Wvt[WELEM];                     // Wv transposed, tf32 [n][k]
__device__ __nv_bfloat16 g_Qh[INELEM];
__device__ __nv_bfloat16 g_Ql[INELEM];
__device__ __nv_bfloat16 g_Kh[INELEM];
__device__ __nv_bfloat16 g_Kl[INELEM];
__device__ float g_V [INELEM];                     // V proj, tf32 bits, [b][t][d]
__device__ float g_Vt[INELEM];                     // V transposed, [b][d][t]
__device__ float g_S[(size_t)BATCH * SEQ * SEQ];   // scores, then tf32 P

// ---------------------------------------------------------------------------
// Helpers
// ---------------------------------------------------------------------------
__device__ __forceinline__ uint32_t smem_u32(const void* p) {
    uint32_t a;
    asm("{ .reg .u64 t; cvta.to.shared.u64 t, %1; cvt.u32.u64 %0, t; }"
        : "=r"(a) : "l"(p));
    return a;
}

#define CP_ASYNC16(saddr, gptr) \
    asm volatile("cp.async.cg.shared.global [%0], [%1], 16;" \
        :: "r"(saddr), "l"(gptr) : "memory")
#define CP_COMMIT() asm volatile("cp.async.commit_group;" ::: "memory")
#define CP_WAIT0()  asm volatile("cp.async.wait_group 0;" ::: "memory")
#define CP_WAIT1()  asm volatile("cp.async.wait_group 1;" ::: "memory")

#define LDSM_X4(r0, r1, r2, r3, addr) \
    asm volatile("ldmatrix.sync.aligned.m8n8.x4.shared.b16 {%0,%1,%2,%3}, [%4];" \
        : "=r"(r0), "=r"(r1), "=r"(r2), "=r"(r3) : "r"(addr))

__device__ __forceinline__ uint32_t to_tf32(float x) {
    uint32_t t;
    asm("cvt.rna.tf32.f32 %0, %1;" : "=r"(t) : "f"(x));
    return t;
}

__device__ __forceinline__ void split_bf16(float x, __nv_bfloat16& h, __nv_bfloat16& l) {
    h = __float2bfloat16_rn(x);
    l = __float2bfloat16_rn(x - __bfloat162float(h));
}

// D += A(16x8 tf32) * B(8x8 tf32), fp32 accumulate
__device__ __forceinline__ void mma8(float* d, const uint32_t* a, const uint32_t* b) {
    asm volatile(
        "mma.sync.aligned.m16n8k8.row.col.f32.tf32.tf32.f32 "
        "{%0,%1,%2,%3}, {%4,%5,%6,%7}, {%8,%9}, {%0,%1,%2,%3};"
        : "+f"(d[0]), "+f"(d[1]), "+f"(d[2]), "+f"(d[3])
        : "r"(a[0]), "r"(a[1]), "r"(a[2]), "r"(a[3]), "r"(b[0]), "r"(b[1]));
}

// D += A(16x16 bf16) * B(16x8 bf16), fp32 accumulate
__device__ __forceinline__ void mma16bf(float* d, const uint32_t* a, const uint32_t* b) {
    asm volatile(
        "mma.sync.aligned.m16n8k16.row.col.f32.bf16.bf16.f32 "
        "{%0,%1,%2,%3}, {%4,%5,%6,%7}, {%8,%9}, {%0,%1,%2,%3};"
        : "+f"(d[0]), "+f"(d[1]), "+f"(d[2]), "+f"(d[3])
        : "r"(a[0]), "r"(a[1]), "r"(a[2]), "r"(a[3]), "r"(b[0]), "r"(b[1]));
}

// ===========================================================================
// Pre-pass 1: q,k -> bf16 hi/lo planes; v -> rounded tf32
// ===========================================================================
__global__ __launch_bounds__(256)
void split_in_k(const float* __restrict__ q, const float* __restrict__ k,
                const float* __restrict__ v,
                __nv_bfloat16* __restrict__ oh, __nv_bfloat16* __restrict__ ol,
                float* __restrict__ vt32)
{
    const int z = blockIdx.z;
    const float* src = (z == 0) ? q : ((z == 1) ? k : v);
    const size_t i = ((size_t)blockIdx.x * 256 + threadIdx.x) * 4;
    float4 x = *(const float4*)(src + i);
    if (z < 2) {
        const size_t base = (size_t)z * INELEM;
        __nv_bfloat16 h0, h1, h2, h3, l0, l1, l2, l3;
        split_bf16(x.x, h0, l0);
        split_bf16(x.y, h1, l1);
        split_bf16(x.z, h2, l2);
        split_bf16(x.w, h3, l3);
        __nv_bfloat162 ph0; ph0.x = h0; ph0.y = h1;
        __nv_bfloat162 ph1; ph1.x = h2; ph1.y = h3;
        __nv_bfloat162 pl0; pl0.x = l0; pl0.y = l1;
        __nv_bfloat162 pl1; pl1.x = l2; pl1.y = l3;
        *(__nv_bfloat162*)(oh + base + i)     = ph0;
        *(__nv_bfloat162*)(oh + base + i + 2) = ph1;
        *(__nv_bfloat162*)(ol + base + i)     = pl0;
        *(__nv_bfloat162*)(ol + base + i + 2) = pl1;
    } else {
        float4 o;
        o.x = __uint_as_float(to_tf32(x.x));
        o.y = __uint_as_float(to_tf32(x.y));
        o.z = __uint_as_float(to_tf32(x.z));
        o.w = __uint_as_float(to_tf32(x.w));
        *(float4*)(vt32 + i) = o;
    }
}

// ===========================================================================
// Pre-pass 2: transpose W[k][n] -> [n][k]; Wq,Wk split bf16; Wv rounded tf32
// ===========================================================================
__global__ __launch_bounds__(256)
void split_w_k(const float* __restrict__ Wq, const float* __restrict__ Wk,
               const float* __restrict__ Wv,
               __nv_bfloat16* __restrict__ oh, __nv_bfloat16* __restrict__ ol,
               float* __restrict__ wvt)
{
    const int z = blockIdx.z;
    const float* W = (z == 0) ? Wq : ((z == 1) ? Wk : Wv);
    __shared__ float t[32][33];
    const int kb = blockIdx.y * 32;
    const int nb = blockIdx.x * 32;
    const int tx = threadIdx.x, ty = threadIdx.y;
#pragma unroll
    for (int j = 0; j < 4; j++)
        t[ty + 8 * j][tx] = W[(size_t)(kb + ty + 8 * j) * DMODEL + nb + tx];
    __syncthreads();
#pragma unroll
    for (int j = 0; j < 4; j++) {
        const float val = t[tx][ty + 8 * j];
        const size_t o = (size_t)(nb + ty + 8 * j) * DMODEL + kb + tx;
        if (z < 2) {
            __nv_bfloat16 h, l;
            split_bf16(val, h, l);
            oh[(size_t)z * WELEM + o] = h;
            ol[(size_t)z * WELEM + o] = l;
        } else {
            wvt[o] = __uint_as_float(to_tf32(val));
        }
    }
}

// ===========================================================================
// Pre-pass 3 (post-vproj): transpose V[b][t][d] -> Vt[b][d][t]
// ===========================================================================
__global__ __launch_bounds__(256)
void transpose_v_k(const float* __restrict__ V, float* __restrict__ Vt)
{
    __shared__ float t[32][33];
    const size_t zb = (size_t)blockIdx.z * SEQ * DMODEL;
    const int tb = blockIdx.y * 32;
    const int db = blockIdx.x * 32;
    const int tx = threadIdx.x, ty = threadIdx.y;
#pragma unroll
    for (int j = 0; j < 4; j++)
        t[ty + 8 * j][tx] = V[zb + (size_t)(tb + ty + 8 * j) * DMODEL + db + tx];
    __syncthreads();
#pragma unroll
    for (int j = 0; j < 4; j++)
        Vt[zb + (size_t)(db + ty + 8 * j) * SEQ + tb + tx] = t[tx][ty + 8 * j];
}

// ===========================================================================
// bf16x3 GEMM body with ldmatrix fragment loads (2-stage, R14 config)
//   EPI=0: fp32*alpha   EPI=3: +bias, bf16 hi/lo plane out
// ===========================================================================
#define SC_ROWW    20
#define SC_PLANE_W (128 * SC_ROWW)
#define SC_STAGE_W (4 * SC_PLANE_W)
#define BF3_SMEM_BYTES (2 * SC_STAGE_W * 4)   // 81920

template <int EPI, bool HASBIAS>
__device__ __forceinline__
void bf3_body(const __nv_bfloat16* __restrict__ Ah,
              const __nv_bfloat16* __restrict__ Al,
              const __nv_bfloat16* __restrict__ Bh,
              const __nv_bfloat16* __restrict__ Bl,
              const float* __restrict__ bias,
              float* __restrict__ C,
              __nv_bfloat16* __restrict__ Cbh, __nv_bfloat16* __restrict__ Cbl,
              int K, int ldk, int ldc, float alpha, int row0, int col0)
{
    extern __shared__ float smemf[];
    uint32_t* sm = (uint32_t*)smemf;

    const int tid  = threadIdx.x;
    const int wid  = tid >> 5;
    const int lane = tid & 31;
    const int tg   = lane >> 2;
    const int tk   = lane & 3;
    const int wm   = (wid >> 2) * 64;
    const int wn   = (wid & 3) * 32;

    const uint32_t aOffW = (uint32_t)((wm + (lane & 15)) * SC_ROWW + (lane >> 4) * 4);
    const uint32_t bOffW = (uint32_t)((wn + (lane & 7) + (lane >> 4) * 8) * SC_ROWW
                                      + ((lane >> 3) & 1) * 4);

    float acc[4][4][4];
#pragma unroll
    for (int mt = 0; mt < 4; mt++)
#pragma unroll
        for (int nt = 0; nt < 4; nt++)
#pragma unroll
            for (int e = 0; e < 4; e++) acc[mt][nt][e] = 0.0f;

    auto fill = [&](int st, int k0) {
        const uint32_t base = smem_u32(sm + st * SC_STAGE_W);
#pragma unroll
        for (int j = 0; j < 8; j++) {
            const __nv_bfloat16* src = (j < 2) ? Ah : ((j < 4) ? Al : ((j < 6) ? Bh : Bl));
            const int rb  = (j < 4) ? row0 : col0;
            const int pl  = j >> 1;
            const int t   = tid + (j & 1) * 256;
            const int r   = t >> 2;
            const int c16 = t & 3;
            CP_ASYNC16(base + (uint32_t)(pl * SC_PLANE_W + r * SC_ROWW + c16 * 4) * 4u,
                       src + (size_t)(rb + r) * ldk + k0 + c16 * 8);
        }
        CP_COMMIT();
    };

    auto compute = [&](int st) {
        const uint32_t stb = smem_u32(sm + st * SC_STAGE_W);
        const uint32_t adAh = stb + aOffW * 4u;
        const uint32_t adAl = adAh + SC_PLANE_W * 4u;
        const uint32_t adBh = stb + 2u * SC_PLANE_W * 4u + bOffW * 4u;
        const uint32_t adBl = adBh + SC_PLANE_W * 4u;
#pragma unroll
        for (int s = 0; s < 2; s++) {
            const uint32_t so = (uint32_t)(s * 8) * 4u;
            uint32_t bh[4][2], bl[4][2];
#pragma unroll
            for (int p = 0; p < 2; p++) {
                const uint32_t po = (uint32_t)(p * 16 * SC_ROWW) * 4u;
                LDSM_X4(bh[2 * p][0], bh[2 * p][1], bh[2 * p + 1][0], bh[2 * p + 1][1],
                        adBh + po + so);
                LDSM_X4(bl[2 * p][0], bl[2 * p][1], bl[2 * p + 1][0], bl[2 * p + 1][1],
                        adBl + po + so);
            }
#pragma unroll
            for (int mt = 0; mt < 4; mt++) {
                const uint32_t mo = (uint32_t)(mt * 16 * SC_ROWW) * 4u;
                uint32_t ah[4], al[4];
                LDSM_X4(ah[0], ah[1], ah[2], ah[3], adAh + mo + so);
                LDSM_X4(al[0], al[1], al[2], al[3], adAl + mo + so);
#pragma unroll
                for (int nt = 0; nt < 4; nt++) mma16bf(acc[mt][nt], ah, bh[nt]);
#pragma unroll
                for (int nt = 0; nt < 4; nt++) mma16bf(acc[mt][nt], ah, bl[nt]);
#pragma unroll
                for (int nt = 0; nt < 4; nt++) mma16bf(acc[mt][nt], al, bh[nt]);
            }
        }
    };

    const int nchunk = K / 32;
    fill(0, 0);
    for (int i = 0; i < nchunk; i++) {
        CP_WAIT0();
        __syncthreads();
        if (i + 1 < nchunk) fill((i + 1) & 1, (i + 1) * 32);
        compute(i & 1);
    }

#pragma unroll
    for (int mt = 0; mt < 4; mt++) {
        const int r = row0 + wm + mt * 16 + tg;
#pragma unroll
        for (int nt = 0; nt < 4; nt++) {
            const int col = col0 + wn + nt * 8 + tk * 2;
            float v[4];
            v[0] = acc[mt][nt][0] * alpha;
            v[1] = acc[mt][nt][1] * alpha;
            v[2] = acc[mt][nt][2] * alpha;
            v[3] = acc[mt][nt][3] * alpha;
            if (HASBIAS) {
                const float b0 = bias[col], b1 = bias[col + 1];
                v[0] += b0; v[1] += b1;
                v[2] += b0; v[3] += b1;
            }
            if (EPI == 3) {
                __nv_bfloat16 h[4], l[4];
#pragma unroll
                for (int e = 0; e < 4; e++) split_bf16(v[e], h[e], l[e]);
                __nv_bfloat162 ph0; ph0.x = h[0]; ph0.y = h[1];
                __nv_bfloat162 pl0; pl0.x = l[0]; pl0.y = l[1];
                __nv_bfloat162 ph1; ph1.x = h[2]; ph1.y = h[3];
                __nv_bfloat162 pl1; pl1.x = l[2]; pl1.y = l[3];
                *(__nv_bfloat162*)(Cbh + (size_t)r * ldc + col)       = ph0;
                *(__nv_bfloat162*)(Cbl + (size_t)r * ldc + col)       = pl0;
                *(__nv_bfloat162*)(Cbh + (size_t)(r + 8) * ldc + col) = ph1;
                *(__nv_bfloat162*)(Cbl + (size_t)(r + 8) * ldc + col) = pl1;
            } else {
                *(float2*)(C + (size_t)r * ldc + col)       = make_float2(v[0], v[1]);
                *(float2*)(C + (size_t)(r + 8) * ldc + col) = make_float2(v[2], v[3]);
            }
        }
    }
}

// ---------------------------------------------------------------------------
// Q,K projections: bf16x3 + ldmatrix. grid (8, 64, 2)
// ---------------------------------------------------------------------------
__global__ __launch_bounds__(256, 2)
void proj_qk_k(const __nv_bfloat16* __restrict__ INh,
               const __nv_bfloat16* __restrict__ INl,
               const __nv_bfloat16* __restrict__ Wh,
               const __nv_bfloat16* __restrict__ Wl,
               const float* __restrict__ bq, const float* __restrict__ bk,
               __nv_bfloat16* __restrict__ Qh, __nv_bfloat16* __restrict__ Ql,
               __nv_bfloat16* __restrict__ Kh, __nv_bfloat16* __restrict__ Kl)
{
    const int z = blockIdx.z;
    const __nv_bfloat16* Ah = INh + (size_t)z * INELEM;
    const __nv_bfloat16* Al = INl + (size_t)z * INELEM;
    const __nv_bfloat16* Bh = Wh + (size_t)z * WELEM;
    const __nv_bfloat16* Bl = Wl + (size_t)z * WELEM;
    const int row0 = blockIdx.y * 128;
    const int col0 = blockIdx.x * 128;
    if (z == 0)
        bf3_body<3, true>(Ah, Al, Bh, Bl, bq, nullptr, Qh, Ql,
                          DMODEL, DMODEL, DMODEL, 1.0f, row0, col0);
    else
        bf3_body<3, true>(Ah, Al, Bh, Bl, bk, nullptr, Kh, Kl,
                          DMODEL, DMODEL, DMODEL, 1.0f, row0, col0);
}

// ---------------------------------------------------------------------------
// Scores: bf16x3 + ldmatrix. grid (16, 16, 4)
// ---------------------------------------------------------------------------
__global__ __launch_bounds__(256, 2)
void scores_k(const __nv_bfloat16* __restrict__ Qh,
              const __nv_bfloat16* __restrict__ Ql,
              const __nv_bfloat16* __restrict__ Kh,
              const __nv_bfloat16* __restrict__ Kl,
              float* __restrict__ Sg)
{
    const size_t zo = (size_t)blockIdx.z * SEQ * DMODEL;
    bf3_body<0, false>(Qh + zo, Ql + zo, Kh + zo, Kl + zo, nullptr,
                       Sg + (size_t)blockIdx.z * SEQ * SEQ, nullptr, nullptr,
                       DMODEL, DMODEL, SEQ, 8.0f,
                       blockIdx.y * 128, blockIdx.x * 128);
}

// ===========================================================================
// tf32 x1 body: A [m][k] k-contig, B [n][k] k-contig, both pre-rounded tf32.
// Fragments via ldmatrix b16 reinterpretation. 3-stage, conversion-free.
//   EPI=0: fp32 out   EPI=1: +bias, rna-tf32 out
// ===========================================================================
#define PV_ROWW    36
#define PV_TILE_W  (128 * PV_ROWW)
#define PV_STAGE_W (2 * PV_TILE_W)
#define PV_SMEM_BYTES (3 * PV_STAGE_W * 4)   // 110592

template <bool HASBIAS, int EPI>
__device__ __forceinline__
void t32_body(const float* __restrict__ A, const float* __restrict__ Bt,
              const float* __restrict__ bias, float* __restrict__ C,
              int K, int lda, int ldb, int ldc, int row0, int col0)
{
    extern __shared__ float smem[];
    uint32_t* sm = (uint32_t*)smem;

    const int tid  = threadIdx.x;
    const int wid  = tid >> 5;
    const int lane = tid & 31;
    const int tg   = lane >> 2;
    const int tk   = lane & 3;
    const int wm   = (wid >> 2) * 64;
    const int wn   = (wid & 3) * 32;

    const uint32_t aOffW = (uint32_t)((wm + (lane & 15)) * PV_ROWW + (lane >> 4) * 4);
    const uint32_t bOffW = (uint32_t)((wn + (lane & 7) + (lane >> 4) * 8) * PV_ROWW
                                      + ((lane >> 3) & 1) * 4);

    float acc[4][4][4];
#pragma unroll
    for (int mt = 0; mt < 4; mt++)
#pragma unroll
        for (int nt = 0; nt < 4; nt++)
#pragma unroll
            for (int e = 0; e < 4; e++) acc[mt][nt][e] = 0.0f;

    auto fill = [&](int st, int k0) {
        const uint32_t base = smem_u32(sm + st * PV_STAGE_W);
#pragma unroll
        for (int j = 0; j < 4; j++) {
            const int idx = tid + j * 256;
            const int r  = idx >> 3;
            const int c4 = (idx & 7) << 2;
            CP_ASYNC16(base + (uint32_t)(r * PV_ROWW + c4) * 4u,
                       A + (size_t)(row0 + r) * lda + k0 + c4);
        }
#pragma unroll
        for (int j = 0; j < 4; j++) {
            const int idx = tid + j * 256;
            const int r  = idx >> 3;
            const int c4 = (idx & 7) << 2;
            CP_ASYNC16(base + (uint32_t)(PV_TILE_W + r * PV_ROWW + c4) * 4u,
                       Bt + (size_t)(col0 + r) * ldb + k0 + c4);
        }
        CP_COMMIT();
    };

    auto compute = [&](int st) {
        const uint32_t stb = smem_u32(sm + st * PV_STAGE_W);
        const uint32_t adA = stb + aOffW * 4u;
        const uint32_t adB = stb + (uint32_t)PV_TILE_W * 4u + bOffW * 4u;
#pragma unroll
        for (int s = 0; s < 4; s++) {
            const uint32_t so = (uint32_t)(s * 8) * 4u;
            uint32_t bh[4][2];
#pragma unroll
            for (int p = 0; p < 2; p++) {
                const uint32_t po = (uint32_t)(p * 16 * PV_ROWW) * 4u;
                LDSM_X4(bh[2 * p][0], bh[2 * p][1], bh[2 * p + 1][0], bh[2 * p + 1][1],
                        adB + po + so);
            }
#pragma unroll
            for (int mt = 0; mt < 4; mt++) {
                const uint32_t mo = (uint32_t)(mt * 16 * PV_ROWW) * 4u;
                uint32_t at[4];
                LDSM_X4(at[0], at[1], at[2], at[3], adA + mo + so);
#pragma unroll
                for (int nt = 0; nt < 4; nt++) mma8(acc[mt][nt], at, bh[nt]);
            }
        }
    };

    const int nchunk = K >> 5;
    fill(0, 0);
    fill(1, 32);
    for (int i = 0; i < nchunk; i++) {
        if (i + 1 < nchunk) { CP_WAIT1(); }
        else                { CP_WAIT0(); }
        __syncthreads();
        if (i + 2 < nchunk) fill((i + 2) % 3, (i + 2) << 5);
        compute(i % 3);
    }

#pragma unroll
    for (int mt = 0; mt < 4; mt++) {
        const int r = row0 + wm + mt * 16 + tg;
#pragma unroll
        for (int nt = 0; nt < 4; nt++) {
            const int col = col0 + wn + nt * 8 + tk * 2;
            float v[4];
            v[0] = acc[mt][nt][0];
            v[1] = acc[mt][nt][1];
            v[2] = acc[mt][nt][2];
            v[3] = acc[mt][nt][3];
            if (HASBIAS) {
                const float b0 = bias[col], b1 = bias[col + 1];
                v[0] += b0; v[1] += b1;
                v[2] += b0; v[3] += b1;
            }
            float2 v0, v1;
            if (EPI == 1) {
                v0 = make_float2(__uint_as_float(to_tf32(v[0])),
                                 __uint_as_float(to_tf32(v[1])));
                v1 = make_float2(__uint_as_float(to_tf32(v[2])),
                                 __uint_as_float(to_tf32(v[3])));
            } else {
                v0 = make_float2(v[0], v[1]);
                v1 = make_float2(v[2], v[3]);
            }
            *(float2*)(C + (size_t)r * ldc + col)       = v0;
            *(float2*)(C + (size_t)(r + 8) * ldc + col) = v1;
        }
    }
}

// ---------------------------------------------------------------------------
// V projection: tf32 x1 (v and Wv pre-rounded). grid (8, 64, 1)
// ---------------------------------------------------------------------------
__global__ __launch_bounds__(256, 2)
void vproj_k(const float* __restrict__ Vin, const float* __restrict__ Wvt,
             const float* __restrict__ bv, float* __restrict__ V)
{
    t32_body<true, 1>(Vin, Wvt, bv, V, DMODEL, DMODEL, DMODEL, DMODEL,
                      blockIdx.y * 128, blockIdx.x * 128);
}

// ---------------------------------------------------------------------------
// PV: tf32 x1 (P row-major tf32, Vt [d][t] tf32). grid (8, 16, 4)
// ---------------------------------------------------------------------------
__global__ __launch_bounds__(256, 2)
void pv_k(const float* __restrict__ Pg, const float* __restrict__ Vt,
          float* __restrict__ Og)
{
    const size_t z = blockIdx.z;
    t32_body<false, 0>(Pg + z * SEQ * SEQ, Vt + z * SEQ * DMODEL, nullptr,
                       Og + z * SEQ * DMODEL, SEQ, SEQ, SEQ, DMODEL,
                       blockIdx.y * 128, blockIdx.x * 128);
}

// ---------------------------------------------------------------------------
// JAX threefry2x32, key (0,42), partitionable scheme
// ---------------------------------------------------------------------------
__device__ __forceinline__ uint32_t threefry_mask_word(uint32_t idx)
{
    const uint32_t ks0 = 0u;
    const uint32_t ks1 = 42u;
    const uint32_t ks2 = 42u ^ 0x1BD11BDAu;
    uint32_t x0 = ks0;
    uint32_t x1 = idx + ks1;
#define TFR(r) { x0 += x1; x1 = __funnelshift_l(x1, x1, (r)); x1 ^= x0; }
    TFR(13) TFR(15) TFR(26) TFR(6)
    x0 += ks1; x1 += ks2 + 1u;
    TFR(17) TFR(29) TFR(16) TFR(24)
    x0 += ks2; x1 += ks0 + 2u;
    TFR(13) TFR(15) TFR(26) TFR(6)
    x0 += ks0; x1 += ks1 + 3u;
    TFR(17) TFR(29) TFR(16) TFR(24)
    x0 += ks1; x1 += ks2 + 4u;
    TFR(13) TFR(15) TFR(26) TFR(6)
    x0 += ks2; x1 += ks0 + 5u;
#undef TFR
    return x0 ^ x1;
}

// ---------------------------------------------------------------------------
// Softmax + dropout; P written pre-rounded tf32
// ---------------------------------------------------------------------------
__global__ __launch_bounds__(256, 4)
void softmax_dropout_k(float* __restrict__ S)
{
    const int q   = blockIdx.x;
    const int b   = blockIdx.y;
    const int tid = threadIdx.x;
    float* __restrict__ row = S + ((size_t)b * SEQ + q) * SEQ;

    float a[8];
#pragma unroll
    for (int j = 0; j < 8; j++) a[j] = row[tid + j * 256];

    float m = a[0];
#pragma unroll
    for (int j = 1; j < 8; j++) m = fmaxf(m, a[j]);
#pragma unroll
    for (int s = 16; s > 0; s >>= 1)
        m = fmaxf(m, __shfl_xor_sync(0xffffffffu, m, s));
    __shared__ float red[8];
    const int wid = tid >> 5, lane = tid & 31;
    if (lane == 0) red[wid] = m;
    __syncthreads();
    m = red[0];
#pragma unroll
    for (int w = 1; w < 8; w++) m = fmaxf(m, red[w]);
    __syncthreads();

    float s0 = 0.0f;
#pragma unroll
    for (int j = 0; j < 8; j++) {
        a[j] = __expf(a[j] - m);
        s0 += a[j];
    }
#pragma unroll
    for (int s = 16; s > 0; s >>= 1)
        s0 += __shfl_xor_sync(0xffffffffu, s0, s);
    if (lane == 0) red[wid] = s0;
    __syncthreads();
    s0 = 0.0f;
#pragma unroll
    for (int w = 0; w < 8; w++) s0 += red[w];

    const float inv = 2.0f / s0;

    const uint32_t base = ((uint32_t)(b * SEQ + q)) * (uint32_t)SEQ;
#pragma unroll
    for (int j = 0; j < 8; j++) {
        const uint32_t k = (uint32_t)tid + (uint32_t)j * 256u;
        const uint32_t w = threefry_mask_word(base + k);
        const float val = (w >> 31) ? 0.0f : a[j] * inv;
        row[k] = __uint_as_float(to_tf32(val));
    }
}

// ---------------------------------------------------------------------------
// Launcher
// ---------------------------------------------------------------------------
extern "C" void kernel_launch(void* const* d_in, const int* in_sizes, int n_in,
                              void* d_out, int out_size)
{
    (void)in_sizes; (void)n_in; (void)out_size;
    const float* query = (const float*)d_in[0];
    const float* key_  = (const float*)d_in[1];
    const float* value = (const float*)d_in[2];
    const float* Wq    = (const float*)d_in[3];
    const float* bq    = (const float*)d_in[4];
    const float* Wk    = (const float*)d_in[5];
    const float* bk    = (const float*)d_in[6];
    const float* Wv    = (const float*)d_in[7];
    const float* bv    = (const float*)d_in[8];
    float* out = (float*)d_out;

    __nv_bfloat16 *dINh, *dINl, *dWh, *dWl, *dQh, *dQl, *dKh, *dKl;
    float *dVin, *dWvt, *dV, *dVt, *dS;
    cudaGetSymbolAddress((void**)&dINh, g_INh);
    cudaGetSymbolAddress((void**)&dINl, g_INl);
    cudaGetSymbolAddress((void**)&dVin, g_Vin);
    cudaGetSymbolAddress((void**)&dWh,  g_Wh);
    cudaGetSymbolAddress((void**)&dWl,  g_Wl);
    cudaGetSymbolAddress((void**)&dWvt, g_Wvt);
    cudaGetSymbolAddress((void**)&dQh,  g_Qh);
    cudaGetSymbolAddress((void**)&dQl,  g_Ql);
    cudaGetSymbolAddress((void**)&dKh,  g_Kh);
    cudaGetSymbolAddress((void**)&dKl,  g_Kl);
    cudaGetSymbolAddress((void**)&dV,   g_V);
    cudaGetSymbolAddress((void**)&dVt,  g_Vt);
    cudaGetSymbolAddress((void**)&dS,   g_S);

    static bool attr_done = false;
    if (!attr_done) {
        cudaFuncSetAttribute(proj_qk_k,
                             cudaFuncAttributeMaxDynamicSharedMemorySize, BF3_SMEM_BYTES);
        cudaFuncSetAttribute(scores_k,
                             cudaFuncAttributeMaxDynamicSharedMemorySize, BF3_SMEM_BYTES);
        cudaFuncSetAttribute(vproj_k,
                             cudaFuncAttributeMaxDynamicSharedMemorySize, PV_SMEM_BYTES);
        cudaFuncSetAttribute(pv_k,
                             cudaFuncAttributeMaxDynamicSharedMemorySize, PV_SMEM_BYTES);
        attr_done = true;
    }

    dim3 thr(256);

    // 0a) q,k -> bf16 planes; v -> rounded tf32
    dim3 gSI(INELEM / (256 * 4), 1, 3);
    split_in_k<<<gSI, thr>>>(query, key_, value, dINh, dINl, dVin);

    // 0b) W transpose: Wq,Wk -> bf16 planes [n][k]; Wv -> tf32 [n][k]
    dim3 gSW(DMODEL / 32, DMODEL / 32, 3);
    split_w_k<<<gSW, dim3(32, 8)>>>(Wq, Wk, Wv, dWh, dWl, dWvt);

    // 1a) Q,K projections — bf16x3 + ldmatrix
    dim3 gP(DMODEL / 128, (BATCH * SEQ) / 128, 2);
    proj_qk_k<<<gP, thr, BF3_SMEM_BYTES>>>(dINh, dINl, dWh, dWl,
                                           bq, bk, dQh, dQl, dKh, dKl);

    // 1b) V projection — tf32 x1 (3x fewer MMAs), tf32-rounded out
    dim3 gVP(DMODEL / 128, (BATCH * SEQ) / 128, 1);
    vproj_k<<<gVP, thr, PV_SMEM_BYTES>>>(dVin, dWvt, bv, dV);

    // 1c) transpose V -> Vt [b][d][t] for PV fragments
    dim3 gTV(DMODEL / 32, SEQ / 32, BATCH);
    transpose_v_k<<<gTV, dim3(32, 8)>>>(dV, dVt);

    // 2) Scores — bf16x3 + ldmatrix
    dim3 gS(SEQ / 128, SEQ / 128, BATCH);
    scores_k<<<gS, thr, BF3_SMEM_BYTES>>>(dQh, dQl, dKh, dKl, dS);

    // 3) Softmax + threefry dropout; P pre-rounded tf32
    dim3 gSm(SEQ, BATCH, 1);
    softmax_dropout_k<<<gSm, thr>>>(dS);

    // 4) O = P @ Vt — tf32 x1 + ldmatrix
    dim3 gO(DMODEL / 128, SEQ / 128, BATCH);
    pv_k<<<gO, thr, PV_SMEM_BYTES>>>(dS, dVt, out);
}